// round 4
// baseline (speedup 1.0000x reference)
#include <cuda_runtime.h>
#include <cstdint>

#define LL 2048
#define BB 32
#define HH 1024
#define MM (LL*BB)

// ---------------- device scratch ----------------
__device__ float g_pstT[HH*BB];     // pstT[n*32+b] = state@W2^T + w2_b + w1_b
__device__ float g_score[MM];       // scores [l*B+b]
__device__ float g_cpart[32*BB*HH]; // context partials

// ---------------- PTX helpers ----------------
__device__ __forceinline__ uint32_t smem_u32(const void* p){
    uint32_t a;
    asm("{ .reg .u64 t; cvta.to.shared.u64 t, %1; cvt.u32.u64 %0, t; }" : "=r"(a) : "l"(p));
    return a;
}
__device__ __forceinline__ void cp16(uint32_t dst, const void* src){
    asm volatile("cp.async.ca.shared.global [%0], [%1], 16;" :: "r"(dst), "l"(src));
}
__device__ __forceinline__ void cp_commit(){ asm volatile("cp.async.commit_group;" ::: "memory"); }
__device__ __forceinline__ void cp_wait1(){ asm volatile("cp.async.wait_group 1;" ::: "memory"); }
__device__ __forceinline__ void cp_wait0(){ asm volatile("cp.async.wait_group 0;" ::: "memory"); }
__device__ __forceinline__ uint32_t f2tf(float x){
    uint32_t r; asm("cvt.rna.tf32.f32 %0, %1;" : "=r"(r) : "f"(x)); return r;
}
__device__ __forceinline__ void mma_tf32(float* c, uint32_t a0, uint32_t a1, uint32_t a2, uint32_t a3,
                                         uint32_t b0, uint32_t b1){
    asm volatile("mma.sync.aligned.m16n8k8.row.col.f32.tf32.tf32.f32 "
        "{%0,%1,%2,%3}, {%4,%5,%6,%7}, {%8,%9}, {%0,%1,%2,%3};"
        : "+f"(c[0]), "+f"(c[1]), "+f"(c[2]), "+f"(c[3])
        : "r"(a0), "r"(a1), "r"(a2), "r"(a3), "r"(b0), "r"(b1));
}

// ---------------- SMEM layout ----------------
// stage: A 128 rows x 144B (36 floats: 32 data + 4 pad) = 18432
//        B 256 rows x 144B                               = 36864
#define ROWF     36
#define STAGE_SZ 55296
#define OB_OFF   18432
#define O_PST    165888      // 3 stages
#define O_V      199680      // pst 256*33*4 = 33792
#define O_RED    200704      // v 1024
#define SMEM_BYTES 209408    // red 128*17*4 = 8704

// ---------------------------------------------------------------------------
// pstT[n*32+b] = sum_h state[b,h]*w2[n,h] + w2_b[n] + w1_b[n]
// ---------------------------------------------------------------------------
__global__ void pstT_kernel(const float* __restrict__ state, const float* __restrict__ w2,
                            const float* __restrict__ w1b, const float* __restrict__ w2b){
    int gw = (blockIdx.x * blockDim.x + threadIdx.x) >> 5;
    int lane = threadIdx.x & 31;
    if (gw >= HH*8) return;
    int n = gw >> 3;
    int b0 = (gw & 7) * 4;
    const float* wr = w2 + (size_t)n * HH;
    float a0=0.f, a1=0.f, a2=0.f, a3=0.f;
    #pragma unroll 4
    for (int h = lane; h < HH; h += 32){
        float w = wr[h];
        a0 += w * state[(b0+0)*HH + h];
        a1 += w * state[(b0+1)*HH + h];
        a2 += w * state[(b0+2)*HH + h];
        a3 += w * state[(b0+3)*HH + h];
    }
    #pragma unroll
    for (int o = 16; o; o >>= 1){
        a0 += __shfl_xor_sync(~0u, a0, o);
        a1 += __shfl_xor_sync(~0u, a1, o);
        a2 += __shfl_xor_sync(~0u, a2, o);
        a3 += __shfl_xor_sync(~0u, a3, o);
    }
    if (lane == 0){
        float bias = w1b[n] + w2b[n];
        g_pstT[n*BB + b0+0] = a0 + bias;
        g_pstT[n*BB + b0+1] = a1 + bias;
        g_pstT[n*BB + b0+2] = a2 + bias;
        g_pstT[n*BB + b0+3] = a3 + bias;
    }
}

// ---------------------------------------------------------------------------
// cp.async one stage: A 128x32 fp32 + B 256x32 fp32 (raw, no conversion)
// ---------------------------------------------------------------------------
__device__ __forceinline__ void cp_stage(uint32_t sb, const float* __restrict__ A,
                                         const float* __restrict__ Wm,
                                         int stage, int m0, int n0, int kt, int tid){
    uint32_t base = sb + stage*STAGE_SZ;
    #pragma unroll
    for (int i = 0; i < 4; ++i){           // A: 1024 chunks
        int idx = tid + i*256;
        int row = idx >> 3, c4 = idx & 7;
        cp16(base + row*144 + c4*16, A + (size_t)(m0+row)*HH + kt*32 + c4*4);
    }
    #pragma unroll
    for (int i = 0; i < 8; ++i){           // B: 2048 chunks
        int idx = tid + i*256;
        int row = idx >> 3, c4 = idx & 7;
        cp16(base + OB_OFF + row*144 + c4*16, Wm + (size_t)(n0+row)*HH + kt*32 + c4*4);
    }
    cp_commit();
}

// ---------------------------------------------------------------------------
// fused single-pass TF32 GEMM + tanh + v-dot
// CTA: 128 M-rows; N in 4 outer tiles of 256. 8 warps (2x4), warp tile 64x64.
// k-permutation: official frag-k kappa -> actual k = (kappa&3)*8 + 4*(kappa>>2) + ks
// (applied identically to A and B => algebra-neutral), making every lane's
// fragment data 8 contiguous floats => conflict-free LDS.128.
// ---------------------------------------------------------------------------
__global__ void __launch_bounds__(256, 1)
gemm_score(const float* __restrict__ A, const float* __restrict__ Wm, const float* __restrict__ v){
    extern __shared__ __align__(128) char smem[];
    uint32_t sb = smem_u32(smem);
    const int tid  = threadIdx.x;
    const int lane = tid & 31;
    const int wid  = tid >> 5;
    const int wm   = wid & 1;       // 2 M-bands of 64
    const int wn   = wid >> 1;      // 4 N-bands of 64
    const int m0   = blockIdx.x * 128;

    float* pst_s = (float*)(smem + O_PST);
    float* v_s   = (float*)(smem + O_V);
    float* red   = (float*)(smem + O_RED);

    for (int i = tid; i < 128*17; i += 256) red[i] = 0.f;
    __syncthreads();

    const int r0 = wm*64 + (lane>>2);
    const int cb = (lane&3)*8;            // float col base within k32 window

    for (int nt = 0; nt < 4; ++nt){
        const int n0 = nt * 256;

        float acc[4][8][4];
        #pragma unroll
        for (int a = 0; a < 4; a++)
            #pragma unroll
            for (int b = 0; b < 8; b++)
                #pragma unroll
                for (int c = 0; c < 4; c++) acc[a][b][c] = 0.f;

        cp_stage(sb, A, Wm, 0, m0, n0, 0, tid);
        cp_stage(sb, A, Wm, 1, m0, n0, 1, tid);

        for (int kt = 0; kt < 32; ++kt){
            if (kt < 30) cp_wait1(); else cp_wait0();
            __syncthreads();
            if (kt + 2 < 32) cp_stage(sb, A, Wm, (kt+2)%3, m0, n0, kt+2, tid);

            const float* sAf = (const float*)(smem + (kt%3)*STAGE_SZ);
            const float* sBf = (const float*)(smem + (kt%3)*STAGE_SZ + OB_OFF);

            // A fragments: 4 mf x (2 rows x 8 contiguous floats)
            uint32_t Au[4][16];
            #pragma unroll
            for (int mf = 0; mf < 4; ++mf){
                const float4* p = (const float4*)(sAf + (r0 + mf*16)*ROWF + cb);
                const float4* q = (const float4*)(sAf + (r0 + mf*16 + 8)*ROWF + cb);
                float4 x0 = p[0], x1 = p[1], y0 = q[0], y1 = q[1];
                Au[mf][0]=f2tf(x0.x); Au[mf][1]=f2tf(x0.y); Au[mf][2]=f2tf(x0.z); Au[mf][3]=f2tf(x0.w);
                Au[mf][4]=f2tf(x1.x); Au[mf][5]=f2tf(x1.y); Au[mf][6]=f2tf(x1.z); Au[mf][7]=f2tf(x1.w);
                Au[mf][8]=f2tf(y0.x); Au[mf][9]=f2tf(y0.y); Au[mf][10]=f2tf(y0.z); Au[mf][11]=f2tf(y0.w);
                Au[mf][12]=f2tf(y1.x); Au[mf][13]=f2tf(y1.y); Au[mf][14]=f2tf(y1.z); Au[mf][15]=f2tf(y1.w);
            }

            #pragma unroll
            for (int nfh = 0; nfh < 2; ++nfh){
                uint32_t Bu[4][8];
                #pragma unroll
                for (int nf2 = 0; nf2 < 4; ++nf2){
                    int n = wn*64 + (nfh*4 + nf2)*8 + (lane>>2);
                    const float4* p = (const float4*)(sBf + n*ROWF + cb);
                    float4 x0 = p[0], x1 = p[1];
                    Bu[nf2][0]=f2tf(x0.x); Bu[nf2][1]=f2tf(x0.y); Bu[nf2][2]=f2tf(x0.z); Bu[nf2][3]=f2tf(x0.w);
                    Bu[nf2][4]=f2tf(x1.x); Bu[nf2][5]=f2tf(x1.y); Bu[nf2][6]=f2tf(x1.z); Bu[nf2][7]=f2tf(x1.w);
                }
                #pragma unroll
                for (int ks = 0; ks < 4; ++ks)
                    #pragma unroll
                    for (int mf = 0; mf < 4; ++mf)
                        #pragma unroll
                        for (int nf2 = 0; nf2 < 4; ++nf2)
                            mma_tf32(acc[mf][nfh*4+nf2],
                                     Au[mf][ks], Au[mf][8+ks], Au[mf][4+ks], Au[mf][12+ks],
                                     Bu[nf2][ks], Bu[nf2][4+ks]);
            }
        }

        // ---- epilogue for this 256-wide N tile ----
        __syncthreads();
        {   // stage pst [256n][32b] (stride 33) and v [256]
            const float4* ps = (const float4*)(g_pstT + n0*BB);
            for (int i = tid; i < 2048; i += 256){
                float4 x = ps[i];
                int n = i >> 3, b4 = (i & 7) * 4;
                pst_s[n*33 + b4+0] = x.x; pst_s[n*33 + b4+1] = x.y;
                pst_s[n*33 + b4+2] = x.z; pst_s[n*33 + b4+3] = x.w;
            }
            if (tid < 256) v_s[tid] = v[n0 + tid];
        }
        __syncthreads();

        #pragma unroll
        for (int mf = 0; mf < 4; ++mf){
            #pragma unroll
            for (int half = 0; half < 2; ++half){
                int row = wm*64 + mf*16 + (lane>>2) + half*8;
                int b   = row & 31;
                float s = 0.f;
                #pragma unroll
                for (int nf = 0; nf < 8; ++nf){
                    #pragma unroll
                    for (int j = 0; j < 2; ++j){
                        int nl = wn*64 + nf*8 + (lane&3)*2 + j;
                        float x = acc[mf][nf][half*2 + j] + pst_s[nl*33 + b];
                        x = fminf(fmaxf(x, -15.f), 15.f);
                        float e = __expf(2.f*x);
                        float t = __fdividef(e - 1.f, e + 1.f);
                        s += v_s[nl] * t;
                    }
                }
                red[row*17 + wn*4 + (lane&3)] += s;
            }
        }
        __syncthreads();
    }

    if (tid < 128){
        const float* r = red + tid*17;
        float s = 0.f;
        #pragma unroll
        for (int j = 0; j < 16; ++j) s += r[j];
        g_score[m0 + tid] = s;
    }
}

// ---------------------------------------------------------------------------
// softmax over L per batch column b; weights -> out + B*H, layout [l*B+b]
// ---------------------------------------------------------------------------
__global__ void softmax_kernel(float* __restrict__ out){
    __shared__ float sdata[256];
    int b = blockIdx.x;
    int tid = threadIdx.x;

    float mx = -1e30f;
    for (int l = tid; l < LL; l += 256) mx = fmaxf(mx, g_score[l*BB + b]);
    sdata[tid] = mx; __syncthreads();
    for (int s = 128; s > 0; s >>= 1){ if (tid < s) sdata[tid] = fmaxf(sdata[tid], sdata[tid+s]); __syncthreads(); }
    mx = sdata[0]; __syncthreads();

    float sum = 0.f;
    for (int l = tid; l < LL; l += 256) sum += __expf(g_score[l*BB + b] - mx);
    sdata[tid] = sum; __syncthreads();
    for (int s = 128; s > 0; s >>= 1){ if (tid < s) sdata[tid] += sdata[tid+s]; __syncthreads(); }
    float inv = 1.f / sdata[0];

    float* w = out + BB*HH;
    for (int l = tid; l < LL; l += 256)
        w[l*BB + b] = __expf(g_score[l*BB + b] - mx) * inv;
}

// ---------------------------------------------------------------------------
// context: 32-way L-split partials, then reduce; float4 over H
// ---------------------------------------------------------------------------
__global__ void ctx_part(const float* __restrict__ enc, const float* __restrict__ wts){
    int s = blockIdx.x;     // 0..31
    int b = blockIdx.y;     // 0..31
    int t = threadIdx.x;    // 0..255 -> float4 over H
    const float4* e = (const float4*)enc;
    float4 acc = make_float4(0.f, 0.f, 0.f, 0.f);
    int l0 = s * 64;
    #pragma unroll 4
    for (int l = 0; l < 64; ++l){
        float w = wts[(l0 + l)*BB + b];
        float4 x = e[((size_t)(l0 + l)*BB + b)*256 + t];
        acc.x += w*x.x; acc.y += w*x.y; acc.z += w*x.z; acc.w += w*x.w;
    }
    ((float4*)g_cpart)[((size_t)s*BB + b)*256 + t] = acc;
}
__global__ void ctx_reduce(float* __restrict__ out){
    int b = blockIdx.x;
    int t = threadIdx.x;
    float4 acc = make_float4(0.f, 0.f, 0.f, 0.f);
    #pragma unroll
    for (int s = 0; s < 32; ++s){
        float4 x = ((const float4*)g_cpart)[((size_t)s*BB + b)*256 + t];
        acc.x += x.x; acc.y += x.y; acc.z += x.z; acc.w += x.w;
    }
    ((float4*)out)[b*256 + t] = acc;
}

// ---------------------------------------------------------------------------
// launch: out = [context (B*H) | att_weights (L*B)]
// ---------------------------------------------------------------------------
extern "C" void kernel_launch(void* const* d_in, const int* in_sizes, int n_in,
                              void* d_out, int out_size) {
    const float* enc = (const float*)d_in[0];
    const float* lds = (const float*)d_in[1];   // state = first B*H floats
    const float* w1w = (const float*)d_in[2];
    const float* w1b = (const float*)d_in[3];
    const float* w2w = (const float*)d_in[4];
    const float* w2b = (const float*)d_in[5];
    const float* vw  = (const float*)d_in[6];
    // v_b cancels under softmax

    float* out = (float*)d_out;

    static bool attr_set = false;
    if (!attr_set){
        cudaFuncSetAttribute(gemm_score, cudaFuncAttributeMaxDynamicSharedMemorySize, SMEM_BYTES);
        attr_set = true;
    }

    pstT_kernel<<<1024, 256>>>(lds, w2w, w1b, w2b);
    gemm_score<<<MM/128, 256, SMEM_BYTES>>>(enc, w1w, vw);
    softmax_kernel<<<BB, 256>>>(out);
    ctx_part<<<dim3(32, BB), 256>>>(enc, out + BB*HH);
    ctx_reduce<<<BB, 256>>>(out);
}

// round 5
// speedup vs baseline: 1.1853x; 1.1853x over previous
#include <cuda_runtime.h>
#include <cstdint>

#define LL 2048
#define BB 32
#define HH 1024
#define MM (LL*BB)

// ---------------- device scratch ----------------
__device__ float g_pstT[HH*BB];     // pstT[n*32+b] = state@W2^T + w2_b + w1_b
__device__ float g_score[MM];       // scores [l*B+b]
__device__ float g_cpart[32*BB*HH]; // context partials

// ---------------- PTX helpers ----------------
__device__ __forceinline__ uint32_t smem_u32(const void* p){
    uint32_t a;
    asm("{ .reg .u64 t; cvta.to.shared.u64 t, %1; cvt.u32.u64 %0, t; }" : "=r"(a) : "l"(p));
    return a;
}
__device__ __forceinline__ void cp16(uint32_t dst, const void* src){
    asm volatile("cp.async.ca.shared.global [%0], [%1], 16;" :: "r"(dst), "l"(src));
}
__device__ __forceinline__ void cp_commit(){ asm volatile("cp.async.commit_group;" ::: "memory"); }
__device__ __forceinline__ void cp_wait2(){ asm volatile("cp.async.wait_group 2;" ::: "memory"); }
__device__ __forceinline__ void cp_wait0(){ asm volatile("cp.async.wait_group 0;" ::: "memory"); }
__device__ __forceinline__ uint32_t f2tf(float x){
    uint32_t r; asm("cvt.rna.tf32.f32 %0, %1;" : "=r"(r) : "f"(x)); return r;
}
__device__ __forceinline__ void mma_tf32(float* c, uint32_t a0, uint32_t a1, uint32_t a2, uint32_t a3,
                                         uint32_t b0, uint32_t b1){
    asm volatile("mma.sync.aligned.m16n8k8.row.col.f32.tf32.tf32.f32 "
        "{%0,%1,%2,%3}, {%4,%5,%6,%7}, {%8,%9}, {%0,%1,%2,%3};"
        : "+f"(c[0]), "+f"(c[1]), "+f"(c[2]), "+f"(c[3])
        : "r"(a0), "r"(a1), "r"(a2), "r"(a3), "r"(b0), "r"(b1));
}
__device__ __forceinline__ float tanh_f(float x){
    float t; asm("tanh.approx.f32 %0, %1;" : "=f"(t) : "f"(x)); return t;
}

// ---------------- SMEM layout ----------------
// stage (k16): A 128 rows x 64B + B 128 rows x 64B = 16384 B ; 4 stages
// NO padding: 8-lane LDS.128 phases span 2 rows = 128B contiguous -> conflict-free
#define STAGE_SZ 16384
#define OB_OFF   8192
#define O_RED    65536
#define SMEM_BYTES 74240     // 4*16384 + 128*17*4

// ---------------------------------------------------------------------------
// pstT[n*32+b] = sum_h state[b,h]*w2[n,h] + w2_b[n] + w1_b[n]
// ---------------------------------------------------------------------------
__global__ void pstT_kernel(const float* __restrict__ state, const float* __restrict__ w2,
                            const float* __restrict__ w1b, const float* __restrict__ w2b){
    int gw = (blockIdx.x * blockDim.x + threadIdx.x) >> 5;
    int lane = threadIdx.x & 31;
    if (gw >= HH*8) return;
    int n = gw >> 3;
    int b0 = (gw & 7) * 4;
    const float* wr = w2 + (size_t)n * HH;
    float a0=0.f, a1=0.f, a2=0.f, a3=0.f;
    #pragma unroll 4
    for (int h = lane; h < HH; h += 32){
        float w = wr[h];
        a0 += w * state[(b0+0)*HH + h];
        a1 += w * state[(b0+1)*HH + h];
        a2 += w * state[(b0+2)*HH + h];
        a3 += w * state[(b0+3)*HH + h];
    }
    #pragma unroll
    for (int o = 16; o; o >>= 1){
        a0 += __shfl_xor_sync(~0u, a0, o);
        a1 += __shfl_xor_sync(~0u, a1, o);
        a2 += __shfl_xor_sync(~0u, a2, o);
        a3 += __shfl_xor_sync(~0u, a3, o);
    }
    if (lane == 0){
        float bias = w1b[n] + w2b[n];
        g_pstT[n*BB + b0+0] = a0 + bias;
        g_pstT[n*BB + b0+1] = a1 + bias;
        g_pstT[n*BB + b0+2] = a2 + bias;
        g_pstT[n*BB + b0+3] = a3 + bias;
    }
}

// ---------------------------------------------------------------------------
// cp.async one k16 stage: A 128x16 fp32 + B 128x16 fp32, 64B rows (no pad)
// ---------------------------------------------------------------------------
__device__ __forceinline__ void cp_stage(uint32_t sb, const float* __restrict__ A,
                                         const float* __restrict__ Wm,
                                         int stage, int m0, int n0, int kt, int tid){
    uint32_t base = sb + stage*STAGE_SZ;
    #pragma unroll
    for (int i = 0; i < 2; ++i){           // A: 512 cp16 chunks
        int idx = tid + i*256;
        int row = idx >> 2, c4 = idx & 3;
        cp16(base + row*64 + c4*16, A + (size_t)(m0+row)*HH + kt*16 + c4*4);
    }
    #pragma unroll
    for (int i = 2; i < 4; ++i){           // B: 512 cp16 chunks
        int idx = tid + (i-2)*256;
        int row = idx >> 2, c4 = idx & 3;
        cp16(base + OB_OFF + row*64 + c4*16, Wm + (size_t)(n0+row)*HH + kt*16 + c4*4);
    }
    cp_commit();
}

// ---------------------------------------------------------------------------
// fused TF32 GEMM + tanh + v-dot
// CTA 128M x (8 x 128N); 8 warps (2x4), warp tile 64x32, k16 stages.
// k-permutation (same for A and B => algebra-neutral): lane q=(lane&3) owns
// smem floats [4q..4q+3] of each k16 half-window => single LDS.128 per row.
// ---------------------------------------------------------------------------
__global__ void __launch_bounds__(256, 2)
gemm_score(const float* __restrict__ A, const float* __restrict__ Wm, const float* __restrict__ v){
    extern __shared__ __align__(128) char smem[];
    uint32_t sb = smem_u32(smem);
    const int tid  = threadIdx.x;
    const int lane = tid & 31;
    const int wid  = tid >> 5;
    const int wm   = wid & 1;       // 2 M-bands of 64
    const int wn   = wid >> 1;      // 4 N-bands of 32
    const int m0   = blockIdx.x * 128;

    float* red = (float*)(smem + O_RED);
    for (int i = tid; i < 128*17; i += 256) red[i] = 0.f;
    __syncthreads();

    const int r0  = wm*64 + (lane>>2);
    const int qb  = (lane&3)*16;          // byte offset of this lane's 4 floats
    const int nb0 = wn*32 + (lane>>2);    // B row base for nf=0

    for (int nt = 0; nt < 8; ++nt){
        const int n0 = nt * 128;

        float acc[4][4][4];
        #pragma unroll
        for (int a = 0; a < 4; a++)
            #pragma unroll
            for (int b = 0; b < 4; b++)
                #pragma unroll
                for (int c = 0; c < 4; c++) acc[a][b][c] = 0.f;

        cp_stage(sb, A, Wm, 0, m0, n0, 0, tid);
        cp_stage(sb, A, Wm, 1, m0, n0, 1, tid);
        cp_stage(sb, A, Wm, 2, m0, n0, 2, tid);

        for (int kt = 0; kt < 64; ++kt){
            if (kt < 62) cp_wait2(); else cp_wait0();
            __syncthreads();
            if (kt + 3 < 64) cp_stage(sb, A, Wm, (kt+3)&3, m0, n0, kt+3, tid);

            const char* sA = smem + (kt&3)*STAGE_SZ;
            const char* sB = sA + OB_OFF;

            // B fragments: 4 nf x one LDS.128 -> 16 tf32 regs
            uint32_t Bu[4][4];
            #pragma unroll
            for (int nf = 0; nf < 4; ++nf){
                float4 g = *(const float4*)(sB + (nb0 + nf*8)*64 + qb);
                Bu[nf][0]=f2tf(g.x); Bu[nf][1]=f2tf(g.y); Bu[nf][2]=f2tf(g.z); Bu[nf][3]=f2tf(g.w);
            }
            #pragma unroll
            for (int mf = 0; mf < 4; ++mf){
                float4 f0 = *(const float4*)(sA + (r0 + mf*16    )*64 + qb);
                float4 f1 = *(const float4*)(sA + (r0 + mf*16 + 8)*64 + qb);
                uint32_t a00=f2tf(f0.x), a01=f2tf(f0.y), a02=f2tf(f0.z), a03=f2tf(f0.w);
                uint32_t a10=f2tf(f1.x), a11=f2tf(f1.y), a12=f2tf(f1.z), a13=f2tf(f1.w);
                #pragma unroll
                for (int nf = 0; nf < 4; ++nf){
                    mma_tf32(acc[mf][nf], a00, a10, a01, a11, Bu[nf][0], Bu[nf][1]);
                    mma_tf32(acc[mf][nf], a02, a12, a03, a13, Bu[nf][2], Bu[nf][3]);
                }
            }
        }

        // epilogue: x = acc + pst; partial score += v * tanh(x)
        #pragma unroll
        for (int mf = 0; mf < 4; ++mf){
            #pragma unroll
            for (int half = 0; half < 2; ++half){
                int row = wm*64 + mf*16 + (lane>>2) + half*8;
                int b   = row & 31;
                float s = 0.f;
                #pragma unroll
                for (int nf = 0; nf < 4; ++nf){
                    #pragma unroll
                    for (int j = 0; j < 2; ++j){
                        int n = n0 + wn*32 + nf*8 + (lane&3)*2 + j;
                        float x = acc[mf][nf][half*2 + j] + g_pstT[n*BB + b];
                        s += v[n] * tanh_f(x);
                    }
                }
                red[row*17 + wn*4 + (lane&3)] += s;
            }
        }
        __syncthreads();
    }

    if (tid < 128){
        const float* r = red + tid*17;
        float s = 0.f;
        #pragma unroll
        for (int j = 0; j < 16; ++j) s += r[j];
        g_score[m0 + tid] = s;
    }
}

// ---------------------------------------------------------------------------
// softmax over L per batch column b; weights -> out + B*H, layout [l*B+b]
// ---------------------------------------------------------------------------
__global__ void softmax_kernel(float* __restrict__ out){
    __shared__ float sdata[256];
    int b = blockIdx.x;
    int tid = threadIdx.x;

    float mx = -1e30f;
    for (int l = tid; l < LL; l += 256) mx = fmaxf(mx, g_score[l*BB + b]);
    sdata[tid] = mx; __syncthreads();
    for (int s = 128; s > 0; s >>= 1){ if (tid < s) sdata[tid] = fmaxf(sdata[tid], sdata[tid+s]); __syncthreads(); }
    mx = sdata[0]; __syncthreads();

    float sum = 0.f;
    for (int l = tid; l < LL; l += 256) sum += __expf(g_score[l*BB + b] - mx);
    sdata[tid] = sum; __syncthreads();
    for (int s = 128; s > 0; s >>= 1){ if (tid < s) sdata[tid] += sdata[tid+s]; __syncthreads(); }
    float inv = 1.f / sdata[0];

    float* w = out + BB*HH;
    for (int l = tid; l < LL; l += 256)
        w[l*BB + b] = __expf(g_score[l*BB + b] - mx) * inv;
}

// ---------------------------------------------------------------------------
// context: 32-way L-split partials, then reduce; float4 over H
// ---------------------------------------------------------------------------
__global__ void ctx_part(const float* __restrict__ enc, const float* __restrict__ wts){
    int s = blockIdx.x;
    int b = blockIdx.y;
    int t = threadIdx.x;
    const float4* e = (const float4*)enc;
    float4 acc = make_float4(0.f, 0.f, 0.f, 0.f);
    int l0 = s * 64;
    #pragma unroll 4
    for (int l = 0; l < 64; ++l){
        float w = wts[(l0 + l)*BB + b];
        float4 x = e[((size_t)(l0 + l)*BB + b)*256 + t];
        acc.x += w*x.x; acc.y += w*x.y; acc.z += w*x.z; acc.w += w*x.w;
    }
    ((float4*)g_cpart)[((size_t)s*BB + b)*256 + t] = acc;
}
__global__ void ctx_reduce(float* __restrict__ out){
    int b = blockIdx.x;
    int t = threadIdx.x;
    float4 acc = make_float4(0.f, 0.f, 0.f, 0.f);
    #pragma unroll
    for (int s = 0; s < 32; ++s){
        float4 x = ((const float4*)g_cpart)[((size_t)s*BB + b)*256 + t];
        acc.x += x.x; acc.y += x.y; acc.z += x.z; acc.w += x.w;
    }
    ((float4*)out)[b*256 + t] = acc;
}

// ---------------------------------------------------------------------------
// launch: out = [context (B*H) | att_weights (L*B)]
// ---------------------------------------------------------------------------
extern "C" void kernel_launch(void* const* d_in, const int* in_sizes, int n_in,
                              void* d_out, int out_size) {
    const float* enc = (const float*)d_in[0];
    const float* lds = (const float*)d_in[1];   // state = first B*H floats
    const float* w1w = (const float*)d_in[2];
    const float* w1b = (const float*)d_in[3];
    const float* w2w = (const float*)d_in[4];
    const float* w2b = (const float*)d_in[5];
    const float* vw  = (const float*)d_in[6];
    // v_b cancels under softmax

    float* out = (float*)d_out;

    static bool attr_set = false;
    if (!attr_set){
        cudaFuncSetAttribute(gemm_score, cudaFuncAttributeMaxDynamicSharedMemorySize, SMEM_BYTES);
        attr_set = true;
    }

    pstT_kernel<<<1024, 256>>>(lds, w2w, w1b, w2b);
    gemm_score<<<MM/128, 256, SMEM_BYTES>>>(enc, w1w, vw);
    softmax_kernel<<<BB, 256>>>(out);
    ctx_part<<<dim3(32, BB), 256>>>(enc, out + BB*HH);
    ctx_reduce<<<BB, 256>>>(out);
}

// round 6
// speedup vs baseline: 1.2485x; 1.0533x over previous
#include <cuda_runtime.h>
#include <cstdint>

#define LL 2048
#define BB 32
#define HH 1024
#define MM (LL*BB)

// ---------------- device scratch ----------------
__device__ float2 g_pstP[(HH/2)*BB];  // pstP[np*32+b] = (pst[2np][b], pst[2np+1][b]), bias folded
__device__ float g_score[MM];         // scores [l*B+b]
__device__ float g_cpart[32*BB*HH];   // context partials

// ---------------- PTX helpers ----------------
__device__ __forceinline__ uint32_t smem_u32(const void* p){
    uint32_t a;
    asm("{ .reg .u64 t; cvta.to.shared.u64 t, %1; cvt.u32.u64 %0, t; }" : "=r"(a) : "l"(p));
    return a;
}
__device__ __forceinline__ void cp16(uint32_t dst, const void* src){
    asm volatile("cp.async.ca.shared.global [%0], [%1], 16;" :: "r"(dst), "l"(src));
}
__device__ __forceinline__ void cp_commit(){ asm volatile("cp.async.commit_group;" ::: "memory"); }
__device__ __forceinline__ void cp_wait2(){ asm volatile("cp.async.wait_group 2;" ::: "memory"); }
__device__ __forceinline__ void cp_wait0(){ asm volatile("cp.async.wait_group 0;" ::: "memory"); }
__device__ __forceinline__ uint32_t f2tf(float x){
    uint32_t r; asm("cvt.rna.tf32.f32 %0, %1;" : "=r"(r) : "f"(x)); return r;
}
__device__ __forceinline__ void mma_tf32(float* c, uint32_t a0, uint32_t a1, uint32_t a2, uint32_t a3,
                                         uint32_t b0, uint32_t b1){
    asm volatile("mma.sync.aligned.m16n8k8.row.col.f32.tf32.tf32.f32 "
        "{%0,%1,%2,%3}, {%4,%5,%6,%7}, {%8,%9}, {%0,%1,%2,%3};"
        : "+f"(c[0]), "+f"(c[1]), "+f"(c[2]), "+f"(c[3])
        : "r"(a0), "r"(a1), "r"(a2), "r"(a3), "r"(b0), "r"(b1));
}
// pair tanh via f16x2 MUFU: returns (tanh(x0), tanh(x1))
__device__ __forceinline__ float2 tanh2(float x0, float x1){
    uint32_t h2, t2;
    asm("cvt.rn.f16x2.f32 %0, %1, %2;" : "=r"(h2) : "f"(x1), "f"(x0));   // hi=x1, lo=x0
    asm("tanh.approx.f16x2 %0, %1;" : "=r"(t2) : "r"(h2));
    float r0, r1;
    asm("{.reg .b16 l, h;\n mov.b32 {l, h}, %2;\n cvt.f32.f16 %0, l;\n cvt.f32.f16 %1, h;}"
        : "=f"(r0), "=f"(r1) : "r"(t2));
    return make_float2(r0, r1);
}

// ---------------- SMEM layout ----------------
// stage (k16): A 128 rows x 64B + B 128 rows x 64B = 16384 B ; 4 stages; no pad (conflict-free)
#define STAGE_SZ 16384
#define OB_OFF   8192
#define O_RED    65536
#define SMEM_BYTES 74240     // 4*16384 + 128*17*4

// ---------------------------------------------------------------------------
// pstP[np*32+b] = (pst[2np][b], pst[2np+1][b]); pst[n][b] = state[b]·w2[n] + w2b[n] + w1b[n]
// one warp per (n-pair, b-pair): 4 dot products
// ---------------------------------------------------------------------------
__global__ void pstT_kernel(const float* __restrict__ state, const float* __restrict__ w2,
                            const float* __restrict__ w1b, const float* __restrict__ w2b){
    int gw = (blockIdx.x * blockDim.x + threadIdx.x) >> 5;
    int lane = threadIdx.x & 31;
    if (gw >= (HH/2)*(BB/2)) return;
    int np = gw >> 4;           // n-pair 0..511
    int b0 = (gw & 15) * 2;     // b base
    int n0 = np * 2;
    const float* w0 = w2 + (size_t)n0 * HH;
    const float* w1r = w2 + (size_t)(n0+1) * HH;
    const float* s0 = state + b0*HH;
    const float* s1 = state + (b0+1)*HH;
    float a00=0.f, a01=0.f, a10=0.f, a11=0.f;
    #pragma unroll 4
    for (int h = lane; h < HH; h += 32){
        float x0 = s0[h], x1 = s1[h];
        float u = w0[h], w = w1r[h];
        a00 += u*x0; a01 += u*x1;
        a10 += w*x0; a11 += w*x1;
    }
    #pragma unroll
    for (int o = 16; o; o >>= 1){
        a00 += __shfl_xor_sync(~0u, a00, o);
        a01 += __shfl_xor_sync(~0u, a01, o);
        a10 += __shfl_xor_sync(~0u, a10, o);
        a11 += __shfl_xor_sync(~0u, a11, o);
    }
    if (lane == 0){
        float bias0 = w1b[n0] + w2b[n0];
        float bias1 = w1b[n0+1] + w2b[n0+1];
        g_pstP[np*BB + b0]   = make_float2(a00 + bias0, a10 + bias1);
        g_pstP[np*BB + b0+1] = make_float2(a01 + bias0, a11 + bias1);
    }
}

// ---------------------------------------------------------------------------
// cp.async one k16 stage: A 128x16 fp32 + B 128x16 fp32, 64B rows (no pad)
// ---------------------------------------------------------------------------
__device__ __forceinline__ void cp_stage(uint32_t sb, const float* __restrict__ A,
                                         const float* __restrict__ Wm,
                                         int stage, int m0, int n0, int kt, int tid){
    uint32_t base = sb + stage*STAGE_SZ;
    #pragma unroll
    for (int i = 0; i < 2; ++i){
        int idx = tid + i*256;
        int row = idx >> 2, c4 = idx & 3;
        cp16(base + row*64 + c4*16, A + (size_t)(m0+row)*HH + kt*16 + c4*4);
    }
    #pragma unroll
    for (int i = 2; i < 4; ++i){
        int idx = tid + (i-2)*256;
        int row = idx >> 2, c4 = idx & 3;
        cp16(base + OB_OFF + row*64 + c4*16, Wm + (size_t)(n0+row)*HH + kt*16 + c4*4);
    }
    cp_commit();
}

// ---------------------------------------------------------------------------
// fused TF32 GEMM + f16x2-tanh + v-dot
// CTA 128M x (8 x 128N); 8 warps (2x4), warp tile 64x32, k16 stages.
// ---------------------------------------------------------------------------
__global__ void __launch_bounds__(256, 2)
gemm_score(const float* __restrict__ A, const float* __restrict__ Wm, const float* __restrict__ v){
    extern __shared__ __align__(128) char smem[];
    uint32_t sb = smem_u32(smem);
    const int tid  = threadIdx.x;
    const int lane = tid & 31;
    const int wid  = tid >> 5;
    const int wm   = wid & 1;       // 2 M-bands of 64
    const int wn   = wid >> 1;      // 4 N-bands of 32
    const int m0   = blockIdx.x * 128;

    float* red = (float*)(smem + O_RED);
    for (int i = tid; i < 128*17; i += 256) red[i] = 0.f;
    __syncthreads();

    const int r0  = wm*64 + (lane>>2);
    const int qb  = (lane&3)*16;          // byte offset of this lane's 4 floats
    const int nb0 = wn*32 + (lane>>2);    // B row base for nf=0

    for (int nt = 0; nt < 8; ++nt){
        const int n0 = nt * 128;

        float acc[4][4][4];
        #pragma unroll
        for (int a = 0; a < 4; a++)
            #pragma unroll
            for (int b = 0; b < 4; b++)
                #pragma unroll
                for (int c = 0; c < 4; c++) acc[a][b][c] = 0.f;

        cp_stage(sb, A, Wm, 0, m0, n0, 0, tid);
        cp_stage(sb, A, Wm, 1, m0, n0, 1, tid);
        cp_stage(sb, A, Wm, 2, m0, n0, 2, tid);

        for (int kt = 0; kt < 64; ++kt){
            if (kt < 62) cp_wait2(); else cp_wait0();
            __syncthreads();
            if (kt + 3 < 64) cp_stage(sb, A, Wm, (kt+3)&3, m0, n0, kt+3, tid);

            const char* sA = smem + (kt&3)*STAGE_SZ;
            const char* sB = sA + OB_OFF;

            uint32_t Bu[4][4];
            #pragma unroll
            for (int nf = 0; nf < 4; ++nf){
                float4 g = *(const float4*)(sB + (nb0 + nf*8)*64 + qb);
                Bu[nf][0]=f2tf(g.x); Bu[nf][1]=f2tf(g.y); Bu[nf][2]=f2tf(g.z); Bu[nf][3]=f2tf(g.w);
            }
            #pragma unroll
            for (int mf = 0; mf < 4; ++mf){
                float4 f0 = *(const float4*)(sA + (r0 + mf*16    )*64 + qb);
                float4 f1 = *(const float4*)(sA + (r0 + mf*16 + 8)*64 + qb);
                uint32_t a00=f2tf(f0.x), a01=f2tf(f0.y), a02=f2tf(f0.z), a03=f2tf(f0.w);
                uint32_t a10=f2tf(f1.x), a11=f2tf(f1.y), a12=f2tf(f1.z), a13=f2tf(f1.w);
                #pragma unroll
                for (int nf = 0; nf < 4; ++nf){
                    mma_tf32(acc[mf][nf], a00, a10, a01, a11, Bu[nf][0], Bu[nf][1]);
                    mma_tf32(acc[mf][nf], a02, a12, a03, a13, Bu[nf][2], Bu[nf][3]);
                }
            }
        }

        // ---- epilogue: preload pst pairs (16) + v pairs (4) into regs ----
        // n(j) = n0 + wn*32 + nf*8 + (lane&3)*2 + j ; np = n>>1
        // b(mf,half) = (lane>>2) + bg*8, bg = (mf&1)*2 + half
        float2 pstr[4][4];   // [bg][nf]
        float2 vp[4];        // [nf]
        {
            int npb = (n0 + wn*32) >> 1;
            #pragma unroll
            for (int nf = 0; nf < 4; ++nf){
                int np = npb + nf*4 + (lane&3);
                vp[nf] = *(const float2*)(v + np*2);
                #pragma unroll
                for (int bg = 0; bg < 4; ++bg){
                    int b = (lane>>2) + bg*8;
                    pstr[bg][nf] = __ldg(&g_pstP[np*BB + b]);
                }
            }
        }

        #pragma unroll
        for (int mf = 0; mf < 4; ++mf){
            #pragma unroll
            for (int half = 0; half < 2; ++half){
                int row = wm*64 + mf*16 + (lane>>2) + half*8;
                int bg  = (mf&1)*2 + half;
                float s = 0.f;
                #pragma unroll
                for (int nf = 0; nf < 4; ++nf){
                    float x0 = acc[mf][nf][half*2 + 0] + pstr[bg][nf].x;
                    float x1 = acc[mf][nf][half*2 + 1] + pstr[bg][nf].y;
                    float2 t = tanh2(x0, x1);
                    s = fmaf(vp[nf].x, t.x, s);
                    s = fmaf(vp[nf].y, t.y, s);
                }
                red[row*17 + wn*4 + (lane&3)] += s;
            }
        }
        __syncthreads();
    }

    if (tid < 128){
        const float* r = red + tid*17;
        float s = 0.f;
        #pragma unroll
        for (int j = 0; j < 16; ++j) s += r[j];
        g_score[m0 + tid] = s;
    }
}

// ---------------------------------------------------------------------------
// softmax over L per batch column b; weights -> out + B*H, layout [l*B+b]
// ---------------------------------------------------------------------------
__global__ void softmax_kernel(float* __restrict__ out){
    __shared__ float sdata[256];
    int b = blockIdx.x;
    int tid = threadIdx.x;

    float mx = -1e30f;
    for (int l = tid; l < LL; l += 256) mx = fmaxf(mx, g_score[l*BB + b]);
    sdata[tid] = mx; __syncthreads();
    for (int s = 128; s > 0; s >>= 1){ if (tid < s) sdata[tid] = fmaxf(sdata[tid], sdata[tid+s]); __syncthreads(); }
    mx = sdata[0]; __syncthreads();

    float sum = 0.f;
    for (int l = tid; l < LL; l += 256) sum += __expf(g_score[l*BB + b] - mx);
    sdata[tid] = sum; __syncthreads();
    for (int s = 128; s > 0; s >>= 1){ if (tid < s) sdata[tid] += sdata[tid+s]; __syncthreads(); }
    float inv = 1.f / sdata[0];

    float* w = out + BB*HH;
    for (int l = tid; l < LL; l += 256)
        w[l*BB + b] = __expf(g_score[l*BB + b] - mx) * inv;
}

// ---------------------------------------------------------------------------
// context: 32-way L-split partials, then reduce; float4 over H
// ---------------------------------------------------------------------------
__global__ void ctx_part(const float* __restrict__ enc, const float* __restrict__ wts){
    int s = blockIdx.x;
    int b = blockIdx.y;
    int t = threadIdx.x;
    const float4* e = (const float4*)enc;
    float4 acc = make_float4(0.f, 0.f, 0.f, 0.f);
    int l0 = s * 64;
    #pragma unroll 4
    for (int l = 0; l < 64; ++l){
        float w = wts[(l0 + l)*BB + b];
        float4 x = e[((size_t)(l0 + l)*BB + b)*256 + t];
        acc.x += w*x.x; acc.y += w*x.y; acc.z += w*x.z; acc.w += w*x.w;
    }
    ((float4*)g_cpart)[((size_t)s*BB + b)*256 + t] = acc;
}
__global__ void ctx_reduce(float* __restrict__ out){
    int b = blockIdx.x;
    int t = threadIdx.x;
    float4 acc = make_float4(0.f, 0.f, 0.f, 0.f);
    #pragma unroll
    for (int s = 0; s < 32; ++s){
        float4 x = ((const float4*)g_cpart)[((size_t)s*BB + b)*256 + t];
        acc.x += x.x; acc.y += x.y; acc.z += x.z; acc.w += x.w;
    }
    ((float4*)out)[b*256 + t] = acc;
}

// ---------------------------------------------------------------------------
// launch: out = [context (B*H) | att_weights (L*B)]
// ---------------------------------------------------------------------------
extern "C" void kernel_launch(void* const* d_in, const int* in_sizes, int n_in,
                              void* d_out, int out_size) {
    const float* enc = (const float*)d_in[0];
    const float* lds = (const float*)d_in[1];   // state = first B*H floats
    const float* w1w = (const float*)d_in[2];
    const float* w1b = (const float*)d_in[3];
    const float* w2w = (const float*)d_in[4];
    const float* w2b = (const float*)d_in[5];
    const float* vw  = (const float*)d_in[6];
    // v_b cancels under softmax

    float* out = (float*)d_out;

    static bool attr_set = false;
    if (!attr_set){
        cudaFuncSetAttribute(gemm_score, cudaFuncAttributeMaxDynamicSharedMemorySize, SMEM_BYTES);
        attr_set = true;
    }

    pstT_kernel<<<1024, 256>>>(lds, w2w, w1b, w2b);
    gemm_score<<<MM/128, 256, SMEM_BYTES>>>(enc, w1w, vw);
    softmax_kernel<<<BB, 256>>>(out);
    ctx_part<<<dim3(32, BB), 256>>>(enc, out + BB*HH);
    ctx_reduce<<<BB, 256>>>(out);
}